// round 14
// baseline (speedup 1.0000x reference)
#include <cuda_runtime.h>
#include <cstdint>

#define WDIM 512
#define NPIX (512*512)
#define ZM 30
#define NZP (ZM/2)

typedef unsigned long long ull;
typedef unsigned int uint;

// ---------------- device scratch ----------------
__device__ __align__(16) float2 d_tmpA[(size_t)ZM * NPIX];   // 63 MB
__device__ __align__(16) float2 d_tmpB[(size_t)ZM * NPIX];   // socol, 15 cpx planes
__device__ __align__(16) float  d_q   [(size_t)ZM * NPIX];   // packed colFFT(q), 15 cpx planes
__device__ __align__(16) float  d_fluo[(size_t)ZM * NPIX];   // fluo, reused as Cbuf
__device__ __align__(16) float  d_xyf [(size_t)NPIX * 16];   // 16 MB: hi/lo bf16 pairs
__device__ int   d_part[256];
__device__ float d_cscale;

// ---------------- bf16 split helpers ----------------
__device__ __forceinline__ void split2(float x0, float x1, uint& h, uint& l) {
    uint hp;
    asm("cvt.rn.bf16x2.f32 %0, %1, %2;" : "=r"(hp) : "f"(x1), "f"(x0));
    float h0 = __uint_as_float(hp << 16);
    float h1 = __uint_as_float(hp & 0xffff0000u);
    float l0 = x0 - h0, l1 = x1 - h1;
    asm("cvt.rn.bf16x2.f32 %0, %1, %2;" : "=r"(l) : "f"(l1), "f"(l0));
    h = hp;
}

__device__ __forceinline__ void mma16816(float c[4], const uint a[4], uint2 b) {
    asm("mma.sync.aligned.m16n8k16.row.col.f32.bf16.bf16.f32 "
        "{%0,%1,%2,%3}, {%4,%5,%6,%7}, {%8,%9}, {%0,%1,%2,%3};"
        : "+f"(c[0]), "+f"(c[1]), "+f"(c[2]), "+f"(c[3])
        : "r"(a[0]), "r"(a[1]), "r"(a[2]), "r"(a[3]), "r"(b.x), "r"(b.y));
}

// ---------------- complex helpers ----------------
__device__ __forceinline__ float2 cmul(float2 a, float2 b) {
    return make_float2(fmaf(a.x, b.x, -a.y * b.y), fmaf(a.x, b.y, a.y * b.x));
}
__device__ __forceinline__ float2 cadd(float2 a, float2 b) { return make_float2(a.x + b.x, a.y + b.y); }
__device__ __forceinline__ float2 csub(float2 a, float2 b) { return make_float2(a.x - b.x, a.y - b.y); }

__device__ __forceinline__ int brev3(int j) { return ((j & 1) << 2) | (j & 2) | ((j >> 2) & 1); }
__device__ __forceinline__ int brev6(int t) { return (int)(__brev((unsigned)t) >> 26); }

#define PADI(p) ((p) + ((p) >> 5))
#define CSTRIDE 532

// ---------------- radix-8 butterflies ----------------
template<int DIR>
__device__ __forceinline__ void bf8_0(float2 e[8])
{
    const float d = (DIR > 0) ? 1.0f : -1.0f;
    float2 f[8];
    #pragma unroll
    for (int m = 0; m < 4; m++) {
        float2 u = e[2 * m], v = e[2 * m + 1];
        f[2 * m]     = cadd(u, v);
        f[2 * m + 1] = csub(u, v);
    }
    float2 g[8];
    #pragma unroll
    for (int hh = 0; hh < 2; hh++) {
        int o = 4 * hh;
        float2 v0 = f[o + 2];
        float2 v1 = make_float2(d * f[o + 3].y, -d * f[o + 3].x);
        g[o + 0] = cadd(f[o + 0], v0); g[o + 2] = csub(f[o + 0], v0);
        g[o + 1] = cadd(f[o + 1], v1); g[o + 3] = csub(f[o + 1], v1);
    }
    const float S2 = 0.70710678118654752f;
    float2 v0 = g[4];
    float2 v1 = cmul(g[5], make_float2(S2, -d * S2));
    float2 v2 = make_float2(d * g[6].y, -d * g[6].x);
    float2 v3 = cmul(g[7], make_float2(-S2, -d * S2));
    e[0] = cadd(g[0], v0); e[4] = csub(g[0], v0);
    e[1] = cadd(g[1], v1); e[5] = csub(g[1], v1);
    e[2] = cadd(g[2], v2); e[6] = csub(g[2], v2);
    e[3] = cadd(g[3], v3); e[7] = csub(g[3], v3);
}

template<int DIR>
__device__ __forceinline__ void bf8_g(float2 e[8], float r)
{
    const float d = (DIR > 0) ? 1.0f : -1.0f;
    float s1, c1;
    sincospif(r, &s1, &c1);
    float2 t1 = make_float2(c1, -d * s1);
    float2 t2 = cmul(t1, t1);
    float2 t4 = cmul(t2, t2);

    float2 f[8];
    #pragma unroll
    for (int m = 0; m < 4; m++) {
        float2 v = cmul(e[2 * m + 1], t4);
        f[2 * m]     = cadd(e[2 * m], v);
        f[2 * m + 1] = csub(e[2 * m], v);
    }
    float2 wb1 = make_float2(d * t2.y, -d * t2.x);
    float2 g[8];
    #pragma unroll
    for (int hh = 0; hh < 2; hh++) {
        int o = 4 * hh;
        float2 v0 = cmul(f[o + 2], t2);
        float2 v1 = cmul(f[o + 3], wb1);
        g[o + 0] = cadd(f[o + 0], v0); g[o + 2] = csub(f[o + 0], v0);
        g[o + 1] = cadd(f[o + 1], v1); g[o + 3] = csub(f[o + 1], v1);
    }
    const float S2 = 0.70710678118654752f;
    float2 wc1 = make_float2(S2 * (t1.x + d * t1.y), S2 * (t1.y - d * t1.x));
    float2 wc2 = make_float2(d * t1.y, -d * t1.x);
    float2 wc3 = make_float2(S2 * (-t1.x + d * t1.y), S2 * (-t1.y - d * t1.x));
    float2 v0 = cmul(g[4], t1);
    float2 v1 = cmul(g[5], wc1);
    float2 v2 = cmul(g[6], wc2);
    float2 v3 = cmul(g[7], wc3);
    e[0] = cadd(g[0], v0); e[4] = csub(g[0], v0);
    e[1] = cadd(g[1], v1); e[5] = csub(g[1], v1);
    e[2] = cadd(g[2], v2); e[6] = csub(g[2], v2);
    e[3] = cadd(g[3], v3); e[7] = csub(g[3], v3);
}

template<int DIR, bool PRESYNC>
__device__ __forceinline__ void fft_unit(float2* s, float2 e[8], int t, bool active)
{
    if (active) bf8_0<DIR>(e);
    if (PRESYNC) __syncthreads();
    if (active) {
        int b = brev6(t);
        #pragma unroll
        for (int j = 0; j < 8; j++) s[PADI(8 * b + j)] = e[j];
    }
    __syncthreads();
    if (active) {
        int b2 = t >> 3, k = t & 7;
        #pragma unroll
        for (int j = 0; j < 8; j++) e[j] = s[PADI(b2 * 64 + j * 8 + k)];
        bf8_g<DIR>(e, (float)k * (1.0f / 32.0f));
        #pragma unroll
        for (int j = 0; j < 8; j++) s[PADI(b2 * 64 + j * 8 + k)] = e[j];
    }
    __syncthreads();
    if (active) {
        #pragma unroll
        for (int j = 0; j < 8; j++) e[j] = s[PADI(j * 64 + t)];
        bf8_g<DIR>(e, (float)t * (1.0f / 256.0f));
    }
}

// ---------------- pupil sum ----------------
__global__ void __launch_bounds__(256) pupil_part(const float* __restrict__ pupil) {
    int tid = threadIdx.x, b = blockIdx.x;
    int v = 0;
    #pragma unroll 4
    for (int q = 0; q < 4; q++) {
        int i = b * 1024 + q * 256 + tid;
        v += (pupil[i] > 0.5f) ? 1 : 0;
    }
    #pragma unroll
    for (int o = 16; o; o >>= 1) v += __shfl_xor_sync(0xffffffffu, v, o);
    __shared__ int ws[8];
    if ((tid & 31) == 0) ws[tid >> 5] = v;
    __syncthreads();
    if (tid == 0) {
        int s = 0;
        #pragma unroll
        for (int w = 0; w < 8; w++) s += ws[w];
        d_part[b] = s;
    }
}

__global__ void __launch_bounds__(256) pupil_final() {
    int tid = threadIdx.x;
    int v = d_part[tid];
    #pragma unroll
    for (int o = 16; o; o >>= 1) v += __shfl_xor_sync(0xffffffffu, v, o);
    __shared__ int ws[8];
    if ((tid & 31) == 0) ws[tid >> 5] = v;
    __syncthreads();
    if (tid == 0) {
        int s = 0;
        #pragma unroll
        for (int w = 0; w < 8; w++) s += ws[w];
        d_cscale = (float)(1.0 / (68719476736.0 * (double)s));
    }
}

// ---------------- bilinear xy_feat + bf16 hi/lo split ----------------
__global__ void __launch_bounds__(256) xyfeat_kernel(
    const float* __restrict__ grid, const float* __restrict__ lerp,
    const int* __restrict__ x0, const int* __restrict__ y0,
    const int* __restrict__ x1, const int* __restrict__ y1)
{
    int p = blockIdx.x * 256 + threadIdx.x;
    float2 l = ((const float2*)lerp)[p];
    float lx = l.x, ly = l.y;
    int X0 = x0[p], Y0 = y0[p], X1 = x1[p], Y1 = y1[p];
    float w00 = (1.f - lx) * (1.f - ly);
    float w10 = lx * (1.f - ly);
    float w01 = (1.f - lx) * ly;
    float w11 = lx * ly;
    const float4* g00 = (const float4*)(grid + ((size_t)Y0 * WDIM + X0) * 16);
    const float4* g10 = (const float4*)(grid + ((size_t)Y0 * WDIM + X1) * 16);
    const float4* g01 = (const float4*)(grid + ((size_t)Y1 * WDIM + X0) * 16);
    const float4* g11 = (const float4*)(grid + ((size_t)Y1 * WDIM + X1) * 16);
    float f[16];
    #pragma unroll
    for (int q = 0; q < 4; q++) {
        float4 a = g00[q], b = g10[q], c = g01[q], d = g11[q];
        f[q * 4 + 0] = a.x * w00 + b.x * w10 + c.x * w01 + d.x * w11;
        f[q * 4 + 1] = a.y * w00 + b.y * w10 + c.y * w01 + d.y * w11;
        f[q * 4 + 2] = a.z * w00 + b.z * w10 + c.z * w01 + d.z * w11;
        f[q * 4 + 3] = a.w * w00 + b.w * w10 + c.w * w01 + d.w * w11;
    }
    uint hi[8], lo[8];
    #pragma unroll
    for (int t = 0; t < 8; t++) split2(f[2 * t], f[2 * t + 1], hi[t], lo[t]);
    uint* hip = (uint*)d_xyf;
    uint* lop = hip + (size_t)NPIX * 8;
    ((uint4*)(hip + (size_t)p * 8))[0] = make_uint4(hi[0], hi[1], hi[2], hi[3]);
    ((uint4*)(hip + (size_t)p * 8))[1] = make_uint4(hi[4], hi[5], hi[6], hi[7]);
    ((uint4*)(lop + (size_t)p * 8))[0] = make_uint4(lo[0], lo[1], lo[2], lo[3]);
    ((uint4*)(lop + (size_t)p * 8))[1] = make_uint4(lo[4], lo[5], lo[6], lo[7]);
}

// ---------------- tensor-core MLP (bf16 3-term split) ----------------
__global__ void __launch_bounds__(128) mlp_kernel(
    const float* __restrict__ zarr, const float* __restrict__ zdat,
    const float* __restrict__ w1, const float* __restrict__ b1,
    const float* __restrict__ w2, const float* __restrict__ b2,
    const float* __restrict__ w3, const float* __restrict__ b3)
{
    __shared__ uint2 w1h[4][32], w1l[4][32];     // [n][lane]
    __shared__ uint2 w2h[8][32], w2l[8][32];     // [s*4+n][lane]
    __shared__ float w3s[32];
    __shared__ float b1s[32], b2s[32];
    __shared__ float b3s;

    int tid = threadIdx.x, lane = tid & 31, warp = tid >> 5;
    int gid = lane >> 2, tig = lane & 3;
    int z = blockIdx.y;

    if (warp == 0) {
        float zv = zarr[z];
        float zn = (29.0f * zv) / 30.0f;
        float zfl = floorf(zn);
        int z0 = (int)zfl; z0 = min(max(z0, 0), ZM - 1);
        int z1 = min(z0 + 1, ZM - 1);
        float zl = zn - zfl;

        int ks[4] = { 2 * tig, 2 * tig + 1, 2 * tig + 8, 2 * tig + 9 };
        float zf[4];
        #pragma unroll
        for (int i = 0; i < 4; i++)
            zf[i] = zdat[z0 * 16 + ks[i]] * (1.0f - zl) + zdat[z1 * 16 + ks[i]] * zl;

        #pragma unroll
        for (int n = 0; n < 4; n++) {
            float wv[4];
            #pragma unroll
            for (int i = 0; i < 4; i++) wv[i] = w1[ks[i] * 32 + 8 * n + gid] * zf[i];
            uint h0, l0, h1, l1;
            split2(wv[0], wv[1], h0, l0);
            split2(wv[2], wv[3], h1, l1);
            w1h[n][lane] = make_uint2(h0, h1);
            w1l[n][lane] = make_uint2(l0, l1);
        }
        #pragma unroll
        for (int s = 0; s < 2; s++)
            #pragma unroll
            for (int n = 0; n < 4; n++) {
                float wv[4];
                #pragma unroll
                for (int i = 0; i < 4; i++) wv[i] = w2[(16 * s + ks[i]) * 32 + 8 * n + gid];
                uint h0, l0, h1, l1;
                split2(wv[0], wv[1], h0, l0);
                split2(wv[2], wv[3], h1, l1);
                w2h[s * 4 + n][lane] = make_uint2(h0, h1);
                w2l[s * 4 + n][lane] = make_uint2(l0, l1);
            }
        w3s[lane] = w3[lane];
        b1s[lane] = b1[lane];
        b2s[lane] = b2[lane];
        if (lane == 0) b3s = b3[0];
    }
    __syncthreads();

    const uint* hip = (const uint*)d_xyf;
    const uint* lop = hip + (size_t)NPIX * 8;
    uint pxb = blockIdx.x * 256 + warp * 64;
    float* fout = d_fluo + (size_t)z * NPIX;

    float w3r[8];
    #pragma unroll
    for (int n = 0; n < 4; n++) {
        w3r[2 * n]     = w3s[8 * n + 2 * tig];
        w3r[2 * n + 1] = w3s[8 * n + 2 * tig + 1];
    }
    float bias3 = b3s;

    #pragma unroll
    for (int m = 0; m < 4; m++) {
        uint pb = pxb + m * 16;
        uint r0 = (pb + gid) * 8u;
        uint r1 = (pb + gid + 8) * 8u;
        uint Ah[4], Al[4];
        Ah[0] = hip[r0 + tig];     Ah[1] = hip[r1 + tig];
        Ah[2] = hip[r0 + tig + 4]; Ah[3] = hip[r1 + tig + 4];
        Al[0] = lop[r0 + tig];     Al[1] = lop[r1 + tig];
        Al[2] = lop[r0 + tig + 4]; Al[3] = lop[r1 + tig + 4];

        // layer 1: 16 -> 32
        float acc[4][4];
        #pragma unroll
        for (int n = 0; n < 4; n++) {
            float bb0 = b1s[8 * n + 2 * tig], bb1 = b1s[8 * n + 2 * tig + 1];
            acc[n][0] = bb0; acc[n][1] = bb1; acc[n][2] = bb0; acc[n][3] = bb1;
        }
        #pragma unroll
        for (int n = 0; n < 4; n++) {
            uint2 bh = w1h[n][lane], bl = w1l[n][lane];
            mma16816(acc[n], Ah, bh);
            mma16816(acc[n], Ah, bl);
            mma16816(acc[n], Al, bh);
        }

        // relu + split -> layer-2 A frags
        uint A2h[2][4], A2l[2][4];
        #pragma unroll
        for (int s = 0; s < 2; s++) {
            split2(fmaxf(acc[2*s][0], 0.f),   fmaxf(acc[2*s][1], 0.f),   A2h[s][0], A2l[s][0]);
            split2(fmaxf(acc[2*s][2], 0.f),   fmaxf(acc[2*s][3], 0.f),   A2h[s][1], A2l[s][1]);
            split2(fmaxf(acc[2*s+1][0], 0.f), fmaxf(acc[2*s+1][1], 0.f), A2h[s][2], A2l[s][2]);
            split2(fmaxf(acc[2*s+1][2], 0.f), fmaxf(acc[2*s+1][3], 0.f), A2h[s][3], A2l[s][3]);
        }

        // layer 2: 32 -> 32
        float acc2[4][4];
        #pragma unroll
        for (int n = 0; n < 4; n++) {
            float bb0 = b2s[8 * n + 2 * tig], bb1 = b2s[8 * n + 2 * tig + 1];
            acc2[n][0] = bb0; acc2[n][1] = bb1; acc2[n][2] = bb0; acc2[n][3] = bb1;
        }
        #pragma unroll
        for (int n = 0; n < 4; n++)
            #pragma unroll
            for (int s = 0; s < 2; s++) {
                uint2 bh = w2h[s * 4 + n][lane], bl = w2l[s * 4 + n][lane];
                mma16816(acc2[n], A2h[s], bh);
                mma16816(acc2[n], A2h[s], bl);
                mma16816(acc2[n], A2l[s], bh);
            }

        // layer 3: 32 -> 1 in fp32 scalar (relu fused into the dot product)
        float p0 = 0.0f, p1 = 0.0f;
        #pragma unroll
        for (int n = 0; n < 4; n++) {
            p0 = fmaf(fmaxf(acc2[n][0], 0.f), w3r[2 * n],     p0);
            p0 = fmaf(fmaxf(acc2[n][1], 0.f), w3r[2 * n + 1], p0);
            p1 = fmaf(fmaxf(acc2[n][2], 0.f), w3r[2 * n],     p1);
            p1 = fmaf(fmaxf(acc2[n][3], 0.f), w3r[2 * n + 1], p1);
        }
        p0 += __shfl_xor_sync(0xffffffffu, p0, 1);
        p0 += __shfl_xor_sync(0xffffffffu, p0, 2);
        p1 += __shfl_xor_sync(0xffffffffu, p1, 1);
        p1 += __shfl_xor_sync(0xffffffffu, p1, 2);

        if (tig == 0) {
            fout[pb + gid]     = p0 + bias3;
            fout[pb + gid + 8] = p1 + bias3;
        }
    }
}

// ---------------- radix-8 row pass: 256 threads, 4 rows per block ----------------
// MODE 0: build P = pupil * exp(i*aberr)   (DIR=-1, zp in [0,30))
template<int DIR, int MODE>
__global__ void __launch_bounds__(256) fft_row4(
    const float* __restrict__ rin, const float* __restrict__ aberr,
    float2* __restrict__ cout)
{
    __shared__ float2 sm[4][CSTRIDE];
    int tid = threadIdx.x;
    int u = tid >> 6, t = tid & 63;
    int r = blockIdx.x * 4 + u;
    int zp = blockIdx.y;
    size_t rb = (size_t)zp * NPIX + (size_t)r * WDIM;

    float2 e[8];
    #pragma unroll
    for (int j = 0; j < 8; j++) {
        int n = t + 64 * j;
        float p = rin[(size_t)r * WDIM + n];
        float ab = aberr[rb + n];
        float sn, cs; __sincosf(ab, &sn, &cs);
        e[brev3(j)] = make_float2(p * cs, p * sn);
    }

    fft_unit<DIR, false>(&sm[u][0], e, t, true);

    #pragma unroll
    for (int j = 0; j < 8; j++) cout[rb + j * 64 + t] = e[j];
}

// ---------------- fused colQ pass: 512 threads, 4 columns, plane pair ----------------
__global__ void __launch_bounds__(512) colq_kernel(
    const float2* __restrict__ in, float2* __restrict__ outp)
{
    __shared__ float2 sm[8 * CSTRIDE];
    int tid = threadIdx.x;
    int u = tid >> 6, t = tid & 63;
    int zp = blockIdx.y;
    int col0 = blockIdx.x * 4;

    #pragma unroll
    for (int q = 0; q < 8; q++) {
        int idx = tid + q * 512;
        int c = idx & 3, pl = (idx >> 2) & 1, i = idx >> 3;
        sm[(pl * 4 + c) * CSTRIDE + PADI(i)] =
            in[(size_t)(2 * zp + pl) * NPIX + (size_t)i * WDIM + col0 + c];
    }
    __syncthreads();

    float2* s = sm + u * CSTRIDE;
    float2 e[8];
    #pragma unroll
    for (int j = 0; j < 8; j++) e[brev3(j)] = s[PADI(t + 64 * j)];
    fft_unit<-1, true>(s, e, t, true);
    #pragma unroll
    for (int j = 0; j < 8; j++) s[PADI(j * 64 + t)] = e[j];
    __syncthreads();

    bool act = (u < 4);
    if (act) {
        float2* s0 = sm + u * CSTRIDE;
        float2* s1 = sm + (4 + u) * CSTRIDE;
        #pragma unroll
        for (int j = 0; j < 8; j++) {
            int n = t + 64 * j;
            float2 a0 = s0[PADI(n)];
            float2 a1 = s1[PADI(n)];
            e[brev3(j)] = make_float2(a0.x * a0.x + a0.y * a0.y,
                                      a1.x * a1.x + a1.y * a1.y);
        }
    }
    fft_unit<+1, true>(s, e, t, act);
    if (act) {
        #pragma unroll
        for (int j = 0; j < 8; j++) s[PADI(j * 64 + t)] = e[j];
    }
    __syncthreads();

    #pragma unroll
    for (int q = 0; q < 4; q++) {
        int idx = tid + q * 512;
        int c = idx & 3, i = idx >> 2;
        outp[(size_t)zp * NPIX + (size_t)i * WDIM + col0 + c] =
            sm[c * CSTRIDE + PADI(i)];
    }
}

// ---------------- colfluo: column FFT of packed real plane pair ----------------
// 512 threads, 8 cols per block; stages plane 2zp into .x and 2zp+1 into .y,
// forward col FFT, writes socol[zp].
__global__ void __launch_bounds__(512) colfluo_kernel(
    const float* __restrict__ fluo, float2* __restrict__ outp)
{
    __shared__ float2 sm[8 * CSTRIDE];
    int tid = threadIdx.x;
    int u = tid >> 6, t = tid & 63;
    int zp = blockIdx.y;
    int col0 = blockIdx.x * 8;

    const float* p0 = fluo + (size_t)(2 * zp) * NPIX;
    const float* p1 = p0 + NPIX;
    #pragma unroll
    for (int q = 0; q < 8; q++) {
        int l = tid + q * 512;
        int c = l & 7, i = l >> 3;
        int gi = i * WDIM + col0 + c;
        sm[c * CSTRIDE + PADI(i)].x = p0[gi];
        sm[c * CSTRIDE + PADI(i)].y = p1[gi];
    }
    __syncthreads();

    float2* s = sm + u * CSTRIDE;
    float2 e[8];
    #pragma unroll
    for (int j = 0; j < 8; j++) e[brev3(j)] = s[PADI(t + 64 * j)];
    fft_unit<+1, true>(s, e, t, true);
    #pragma unroll
    for (int j = 0; j < 8; j++) s[PADI(j * 64 + t)] = e[j];
    __syncthreads();

    #pragma unroll
    for (int q = 0; q < 8; q++) {
        int l = tid + q * 512;
        int c = l & 7, i = l >> 3;
        outp[(size_t)zp * NPIX + (size_t)i * WDIM + col0 + c] =
            sm[c * CSTRIDE + PADI(i)];
    }
}

// ---------------- fused crossQ pass: 256 threads, 4 units ----------------
// Units 0,1: forward row FFT of qcol rows (r, 512-r)   -> Sq rows in smem.
// Units 2,3: forward row FFT of socol rows (same rows) -> So rows in smem.
// Phase B (units 0,1): Hermitian cross spectrum + inverse row FFT -> Cbuf.
__global__ void __launch_bounds__(256) crossq_kernel(
    const float2* __restrict__ qcol, const float2* __restrict__ socol,
    float2* __restrict__ cout)
{
    __shared__ float2 sm[4 * CSTRIDE];
    int tid = threadIdx.x;
    int u = tid >> 6, t = tid & 63;
    int b = blockIdx.x;
    int zp = blockIdx.y;
    size_t zb = (size_t)zp * NPIX;

    int ur = u & 1;                                   // row slot within pair
    int ru = (b == 0) ? (ur == 0 ? 0 : 256) : (ur == 0 ? b : WDIM - b);
    int pu = (b == 0) ? ur : 1 - ur;                  // partner row slot
    size_t rb = zb + (size_t)ru * WDIM;

    float2* s = sm + u * CSTRIDE;

    // phase A: forward FFT (u<2: qcol row ru; u>=2: socol row ru)
    const float2* src = (u < 2) ? qcol : socol;
    float2 e[8];
    #pragma unroll
    for (int j = 0; j < 8; j++) e[brev3(j)] = src[rb + t + 64 * j];
    fft_unit<+1, false>(s, e, t, true);
    #pragma unroll
    for (int j = 0; j < 8; j++) s[PADI(j * 64 + t)] = e[j];
    __syncthreads();

    // phase B: cross spectrum + inverse FFT (units 0,1 only)
    bool act = (u < 2);
    if (act) {
        float2* sq  = sm + u * CSTRIDE;
        float2* sqm = sm + pu * CSTRIDE;
        float2* so  = sm + (2 + u) * CSTRIDE;
        float2* som = sm + (2 + pu) * CSTRIDE;
        float sc = 0.25f * d_cscale;
        #pragma unroll
        for (int j = 0; j < 8; j++) {
            int n = t + 64 * j;
            int nn = (WDIM - n) & (WDIM - 1);
            float2 Sq  = sq[PADI(n)];
            float2 Sqm = sqm[PADI(nn)];
            float2 So  = so[PADI(n)];
            float2 Som = som[PADI(nn)];
            float2 Po = make_float2(So.x + Som.x, So.y - Som.y);
            float2 Mo = make_float2(So.x - Som.x, So.y + Som.y);
            float2 Pq = make_float2(Sq.x + Sqm.x, Sq.y - Sqm.y);
            float2 Mq = make_float2(Sq.x - Sqm.x, Sq.y + Sqm.y);
            float2 PP = cmul(Po, Pq);
            float2 MM = cmul(Mo, Mq);
            e[brev3(j)] = make_float2(sc * (PP.x + MM.y), sc * (PP.y - MM.x));
        }
    }
    fft_unit<-1, true>(s, e, t, act);

    if (act) {
        #pragma unroll
        for (int j = 0; j < 8; j++) cout[rb + j * 64 + t] = e[j];
    }
}

// ---------------- radix-8 column pass: 512 threads, 8 cols per block ----------------
// MODE 2: split: rout[2zp]=Re, rout[2zp+1]=Im   (DIR=-1)
template<int DIR, int MODE>
__global__ void __launch_bounds__(512) fft_col8(
    const float2* __restrict__ in, float2* __restrict__ cout, float* __restrict__ rout)
{
    __shared__ float2 sm[8 * CSTRIDE];
    int tid = threadIdx.x;
    int zp = blockIdx.y;
    int col0 = blockIdx.x * 8;
    size_t zb = (size_t)zp * NPIX;

    #pragma unroll
    for (int q = 0; q < 8; q++) {
        int l = tid + q * 512;
        int c = l & 7, i = l >> 3;
        sm[c * CSTRIDE + PADI(i)] = in[zb + (size_t)i * WDIM + col0 + c];
    }
    __syncthreads();

    int u = tid >> 6, t = tid & 63;
    float2* s = sm + u * CSTRIDE;
    float2 e[8];
    #pragma unroll
    for (int j = 0; j < 8; j++) e[brev3(j)] = s[PADI(t + 64 * j)];
    fft_unit<DIR, true>(s, e, t, true);
    #pragma unroll
    for (int j = 0; j < 8; j++) s[PADI(j * 64 + t)] = e[j];
    __syncthreads();

    #pragma unroll
    for (int q = 0; q < 8; q++) {
        int l = tid + q * 512;
        int c = l & 7, i = l >> 3;
        float2 v = sm[c * CSTRIDE + PADI(i)];
        size_t sp = (size_t)i * WDIM + col0 + c;
        if (MODE == 1) {
            cout[zb + sp] = v;
        } else {
            rout[(size_t)(2 * zp) * NPIX + sp]     = v.x;
            rout[(size_t)(2 * zp + 1) * NPIX + sp] = v.y;
        }
    }
}

// ---------------- launcher ----------------
extern "C" void kernel_launch(void* const* d_in, const int* in_sizes, int n_in,
                              void* d_out, int out_size)
{
    const float* z     = (const float*)d_in[0];
    const float* grid  = (const float*)d_in[1];
    const float* zdat  = (const float*)d_in[2];
    const float* w1    = (const float*)d_in[3];
    const float* b1    = (const float*)d_in[4];
    const float* w2    = (const float*)d_in[5];
    const float* b2    = (const float*)d_in[6];
    const float* w3    = (const float*)d_in[7];
    const float* b3    = (const float*)d_in[8];
    const float* pupil = (const float*)d_in[9];
    const float* aberr = (const float*)d_in[10];
    const float* lerp  = (const float*)d_in[11];
    const int*   x0    = (const int*)d_in[12];
    const int*   y0    = (const int*)d_in[13];
    const int*   x1    = (const int*)d_in[14];
    const int*   y1    = (const int*)d_in[15];
    float* out = (float*)d_out;

    float2* tmpA; float2* tmpB; float* qbuf; float* fluo;
    cudaGetSymbolAddress((void**)&tmpA, d_tmpA);
    cudaGetSymbolAddress((void**)&tmpB, d_tmpB);
    cudaGetSymbolAddress((void**)&qbuf, d_q);
    cudaGetSymbolAddress((void**)&fluo, d_fluo);
    float2* qcol  = (float2*)qbuf;   // packed colF(q), 15 cpx planes
    float2* socol = tmpB;            // packed colF(fluo), 15 cpx planes
    float2* Cbuf  = (float2*)fluo;   // reuse fluo after colfluo consumed it

    // Side stream for the pupil path (independent of render path until crossq).
    // Created fresh each call; intentionally NOT destroyed (capture-owned).
    cudaStream_t sA;
    cudaStreamCreateWithFlags(&sA, cudaStreamNonBlocking);
    cudaEvent_t evFork, evJoin;
    cudaEventCreateWithFlags(&evFork, cudaEventDisableTiming);
    cudaEventCreateWithFlags(&evJoin, cudaEventDisableTiming);

    cudaEventRecord(evFork, 0);
    cudaStreamWaitEvent(sA, evFork, 0);

    // ---- side stream: pupil path ----
    pupil_part<<<256, 256, 0, sA>>>(pupil);
    pupil_final<<<1, 256, 0, sA>>>();
    fft_row4<-1, 0><<<dim3(WDIM / 4, ZM), 256, 0, sA>>>(pupil, aberr, tmpA);
    colq_kernel<<<dim3(WDIM / 4, NZP), 512, 0, sA>>>(tmpA, qcol);
    cudaEventRecord(evJoin, sA);

    // ---- main stream: render path ----
    xyfeat_kernel<<<NPIX / 256, 256>>>(grid, lerp, x0, y0, x1, y1);
    mlp_kernel<<<dim3(NPIX / 256, ZM), 128>>>(z, zdat, w1, b1, w2, b2, w3, b3);
    // socol = colF(fluo) packed (So's row FFT happens inside crossq)
    colfluo_kernel<<<dim3(WDIM / 8, NZP), 512>>>(fluo, socol);

    cudaStreamWaitEvent(0, evJoin, 0);

    // Sq rows + So rows (row FFT) + Hermitian cross spectrum + row IFFT -> Cbuf
    crossq_kernel<<<dim3(WDIM / 2, NZP), 256>>>(qcol, socol, Cbuf);
    // inverse col pass, split packed planes into the 30 real output planes
    fft_col8<-1, 2><<<dim3(WDIM / 8, NZP), 512>>>(Cbuf, nullptr, out);
}